// round 9
// baseline (speedup 1.0000x reference)
#include <cuda_runtime.h>

// Problem constants
#define BATCH   8
#define CDIM    512
#define SEQ     1024      // H*W = 32*32
#define NHEADS  8
#define HDIM    64
#define SCALE   0.125f    // 1/sqrt(64)
#define LOG2E   1.44269504088896340736f

typedef unsigned long long ull;
union F2 { ull u; float2 f; };

__device__ __forceinline__ ull pack2(float lo, float hi) {
    ull r; asm("mov.b64 %0, {%1, %2};" : "=l"(r) : "f"(lo), "f"(hi)); return r;
}
__device__ __forceinline__ void fma2(ull &d, ull a, ull b) {
    asm("fma.rn.f32x2 %0, %1, %2, %0;" : "+l"(d) : "l"(a), "l"(b));
}
__device__ __forceinline__ void mul2(ull &d, ull a) {
    asm("mul.rn.f32x2 %0, %1, %2;" : "=l"(d) : "l"(d), "l"(a));
}
__device__ __forceinline__ float ex2(float x) {
    float r; asm("ex2.approx.f32 %0, %1;" : "=f"(r) : "f"(x)); return r;
}

// Scratch for projected Q, K, V in [b][h][s][d] layout (fp32). 16 MB each.
__device__ float g_Q[BATCH * CDIM * SEQ];
__device__ float g_K[BATCH * CDIM * SEQ];
__device__ float g_V[BATCH * CDIM * SEQ];

// ---------------------------------------------------------------------------
// Projection GEMM with packed f32x2 FMAs.
//   BM=128, BN=128, BK=16, 256 threads, 8x8 micro-tile, accumulators packed
//   in pairs along n. BK=16 gives ~700 issue-cycles of compute per barrier
//   so the single-stage global prefetch hides DRAM latency.
// ---------------------------------------------------------------------------
__global__ void __launch_bounds__(256, 2)
proj_kernel(const float* __restrict__ q_in,
            const float* __restrict__ kv_in,
            const float* __restrict__ W,
            const float* __restrict__ bias)
{
    __shared__ float As[16][128];
    __shared__ float Bs[16][128];

    const int proj = blockIdx.z;                   // 0=Q, 1=K, 2=V
    const float* src = (proj == 0) ? q_in : kv_in;
    float* dst = (proj == 0) ? g_Q : ((proj == 1) ? g_K : g_V);

    const int tid = threadIdx.x;
    const int tx  = tid & 15;        // n direction (8 cols each)
    const int ty  = tid >> 4;        // m direction (8 rows each)

    const int b  = blockIdx.y >> 3;
    const int s0 = (blockIdx.y & 7) << 7;
    const int n0 = blockIdx.x << 7;

    const float* Abase = src + b * (CDIM * SEQ) + s0;
    const float* Bbase = W + proj * 512 + n0;

    const int ka = tid >> 5;             // 0..7
    const int ma = (tid & 31) << 2;      // 0..124

    F2 acc2[8][4];                       // [row][col-pair]
#pragma unroll
    for (int i = 0; i < 8; i++)
#pragma unroll
        for (int j = 0; j < 4; j++) acc2[i][j].u = 0ull;

    for (int k0 = 0; k0 < CDIM; k0 += 16) {
        float4 av0 = *(const float4*)(Abase + (k0 + ka) * SEQ + ma);
        float4 av1 = *(const float4*)(Abase + (k0 + ka + 8) * SEQ + ma);
        float4 bv0 = *(const float4*)(Bbase + (k0 + ka) * (3 * CDIM) + ma);
        float4 bv1 = *(const float4*)(Bbase + (k0 + ka + 8) * (3 * CDIM) + ma);
        __syncthreads();
        *(float4*)&As[ka][ma]     = av0;
        *(float4*)&As[ka + 8][ma] = av1;
        *(float4*)&Bs[ka][ma]     = bv0;
        *(float4*)&Bs[ka + 8][ma] = bv1;
        __syncthreads();

#pragma unroll
        for (int kk = 0; kk < 16; kk++) {
            ulonglong2 b01 = *(const ulonglong2*)&Bs[kk][tx * 8];
            ulonglong2 b23 = *(const ulonglong2*)&Bs[kk][tx * 8 + 4];
            ull b2[4] = { b01.x, b01.y, b23.x, b23.y };
            float4 a0 = *(const float4*)&As[kk][ty * 8];
            float4 a1 = *(const float4*)&As[kk][ty * 8 + 4];
            ull as_[8] = { pack2(a0.x, a0.x), pack2(a0.y, a0.y),
                           pack2(a0.z, a0.z), pack2(a0.w, a0.w),
                           pack2(a1.x, a1.x), pack2(a1.y, a1.y),
                           pack2(a1.z, a1.z), pack2(a1.w, a1.w) };
#pragma unroll
            for (int i = 0; i < 8; i++)
#pragma unroll
                for (int j = 0; j < 4; j++)
                    fma2(acc2[i][j].u, as_[i], b2[j]);
        }
    }

    // epilogue: add bias, write to [b][h][s][d]
    const int nbase = n0 + tx * 8;           // multiple of 8 -> one head
    const int h  = nbase >> 6;
    const int d0 = nbase & 63;
    float bv[8];
#pragma unroll
    for (int j = 0; j < 8; j++) bv[j] = bias[proj * 512 + nbase + j];

    float* obase = dst + b * (CDIM * SEQ) + h * (SEQ * HDIM) + d0;
#pragma unroll
    for (int i = 0; i < 8; i++) {
        const int s = s0 + ty * 8 + i;
        float4 v0, v1;
        v0.x = acc2[i][0].f.x + bv[0]; v0.y = acc2[i][0].f.y + bv[1];
        v0.z = acc2[i][1].f.x + bv[2]; v0.w = acc2[i][1].f.y + bv[3];
        v1.x = acc2[i][2].f.x + bv[4]; v1.y = acc2[i][2].f.y + bv[5];
        v1.z = acc2[i][3].f.x + bv[6]; v1.w = acc2[i][3].f.y + bv[7];
        *(float4*)(obase + s * HDIM + 0) = v0;
        *(float4*)(obase + s * HDIM + 4) = v1;
    }
}

// ---------------------------------------------------------------------------
// Flash attention v3: 64 threads/block, 64x64 tiles, 8x8 per-thread
// micro-tile (tx = tid&7 -> 8 keys/d-cols, ty = tid>>3 -> 8 q-rows).
// Accumulators packed over q-row pairs with f32x2 FMAs. 1.0 smem-byte/MAC.
// Softmax in exp2 domain. Row-group = 8 consecutive lanes -> shfl 1/2/4.
//
// Dynamic smem (floats):
//   Qt [64][66]  Q^T tile [d][row], pre-scaled                (4224)
//   Un [64][68]  union: K [key][d] stride 65 / P^T [key][row]
//                stride 66 / O^T [d][row] stride 68           (4352)
//   Vs [64][64]  V tile [key][d]                              (4096)
// Total 50,688 B -> 4 blocks/SM.
// ---------------------------------------------------------------------------
#define QT_STRIDE 66
#define KS_STRIDE 65
#define PT_STRIDE 66
#define OT_STRIDE 68
#define QT_F (64 * QT_STRIDE)
#define U_F  (64 * OT_STRIDE)
#define VS_F (64 * 64)
#define ATTN_SMEM_FLOATS (QT_F + U_F + VS_F)

__global__ void __launch_bounds__(64)
attn_kernel(float* __restrict__ out)
{
    extern __shared__ float sm[];
    float* Qt = sm;                 // [d][row], stride 66
    float* Un = sm + QT_F;          // Ks(65) / Pt(66) / Ot(68)
    float* Vs = sm + QT_F + U_F;    // [key][d], stride 64

    const int tid = threadIdx.x;
    const int tx  = tid & 7;        // 8 keys / 8 d-cols
    const int ty  = tid >> 3;       // 8 q-rows (ty*8 ..)

    const int bh = blockIdx.y;
    const int q0 = blockIdx.x << 6;
    const float* Qp = g_Q + bh * (SEQ * HDIM);
    const float* Kp = g_K + bh * (SEQ * HDIM);
    const float* Vp = g_V + bh * (SEQ * HDIM);

    const float qscale = SCALE * LOG2E;

    // Load Q tile transposed, pre-scaled
#pragma unroll
    for (int it = 0; it < 16; it++) {
        const int id  = tid + it * 64;
        const int row = id >> 4;
        const int d0  = (id & 15) << 2;
        float4 qv = *(const float4*)(Qp + (q0 + row) * HDIM + d0);
        Qt[(d0 + 0) * QT_STRIDE + row] = qv.x * qscale;
        Qt[(d0 + 1) * QT_STRIDE + row] = qv.y * qscale;
        Qt[(d0 + 2) * QT_STRIDE + row] = qv.z * qscale;
        Qt[(d0 + 3) * QT_STRIDE + row] = qv.w * qscale;
    }

    F2 o2[4][8];                    // [row-pair][d-col]
    float m_i[8], l_i[8];
#pragma unroll
    for (int p = 0; p < 4; p++)
#pragma unroll
        for (int j = 0; j < 8; j++) o2[p][j].u = 0ull;
#pragma unroll
    for (int i = 0; i < 8; i++) { m_i[i] = -1e30f; l_i[i] = 0.0f; }

    for (int kt = 0; kt < 16; kt++) {
        const int key0 = kt << 6;
        __syncthreads();            // prev PV done reading Un(Pt)/Vs

        // Load K tile (Un, stride 65) and V tile
#pragma unroll
        for (int it = 0; it < 16; it++) {
            const int id   = tid + it * 64;
            const int krow = id >> 4;
            const int d0   = (id & 15) << 2;
            float4 kv = *(const float4*)(Kp + (key0 + krow) * HDIM + d0);
            Un[krow * KS_STRIDE + d0 + 0] = kv.x;
            Un[krow * KS_STRIDE + d0 + 1] = kv.y;
            Un[krow * KS_STRIDE + d0 + 2] = kv.z;
            Un[krow * KS_STRIDE + d0 + 3] = kv.w;
            float4 vv = *(const float4*)(Vp + (key0 + krow) * HDIM + d0);
            *(float4*)&Vs[krow * 64 + d0] = vv;
        }
        __syncthreads();

        // ---- S = Q*K^T (log2 domain), 8 rows x 8 keys ----
        F2 s2[4][8];
#pragma unroll
        for (int p = 0; p < 4; p++)
#pragma unroll
            for (int j = 0; j < 8; j++) s2[p][j].u = 0ull;

#pragma unroll 8
        for (int kk = 0; kk < 64; kk++) {
            const float* qrow = Qt + kk * QT_STRIDE + ty * 8;
            ull a2[4];
            a2[0] = *(const ull*)(qrow + 0);
            a2[1] = *(const ull*)(qrow + 2);
            a2[2] = *(const ull*)(qrow + 4);
            a2[3] = *(const ull*)(qrow + 6);
#pragma unroll
            for (int j = 0; j < 8; j++) {
                float bj = Un[(tx * 8 + j) * KS_STRIDE + kk];
                ull bb = pack2(bj, bj);
                fma2(s2[0][j].u, a2[0], bb);
                fma2(s2[1][j].u, a2[1], bb);
                fma2(s2[2][j].u, a2[2], bb);
                fma2(s2[3][j].u, a2[3], bb);
            }
        }

        // ---- Online softmax (exp2 domain), rows i = 2p + half ----
        float rm[8], rs[8], alpha[8];
#pragma unroll
        for (int p = 0; p < 4; p++) {
            float mx = s2[p][0].f.x, my = s2[p][0].f.y;
#pragma unroll
            for (int j = 1; j < 8; j++) {
                mx = fmaxf(mx, s2[p][j].f.x);
                my = fmaxf(my, s2[p][j].f.y);
            }
            rm[2*p] = mx; rm[2*p+1] = my;
        }
#pragma unroll
        for (int msk = 1; msk < 8; msk <<= 1)
#pragma unroll
            for (int i = 0; i < 8; i++)
                rm[i] = fmaxf(rm[i], __shfl_xor_sync(0xffffffffu, rm[i], msk));

#pragma unroll
        for (int i = 0; i < 8; i++) {
            float mn = fmaxf(m_i[i], rm[i]);
            alpha[i] = ex2(m_i[i] - mn);
            m_i[i] = mn;
        }
#pragma unroll
        for (int p = 0; p < 4; p++) {
            float sx = 0.0f, sy = 0.0f;
#pragma unroll
            for (int j = 0; j < 8; j++) {
                s2[p][j].f.x = ex2(s2[p][j].f.x - m_i[2*p]);
                s2[p][j].f.y = ex2(s2[p][j].f.y - m_i[2*p+1]);
                sx += s2[p][j].f.x;
                sy += s2[p][j].f.y;
            }
            rs[2*p] = sx; rs[2*p+1] = sy;
        }
#pragma unroll
        for (int msk = 1; msk < 8; msk <<= 1)
#pragma unroll
            for (int i = 0; i < 8; i++)
                rs[i] += __shfl_xor_sync(0xffffffffu, rs[i], msk);
#pragma unroll
        for (int i = 0; i < 8; i++)
            l_i[i] = l_i[i] * alpha[i] + rs[i];
#pragma unroll
        for (int p = 0; p < 4; p++) {
            ull a2p = pack2(alpha[2*p], alpha[2*p+1]);
#pragma unroll
            for (int j = 0; j < 8; j++) mul2(o2[p][j].u, a2p);
        }

        __syncthreads();            // everyone done reading K from Un
        // Stage P^T[key][row] (stride 66, 8B-aligned 64-bit stores)
#pragma unroll
        for (int j = 0; j < 8; j++)
#pragma unroll
            for (int p = 0; p < 4; p++)
                *(ull*)(Un + (tx * 8 + j) * PT_STRIDE + ty * 8 + 2 * p) = s2[p][j].u;
        __syncthreads();

        // ---- O += P*V ----
#pragma unroll 8
        for (int kk = 0; kk < 64; kk++) {
            const float* prow = Un + kk * PT_STRIDE + ty * 8;
            ull a2[4];
            a2[0] = *(const ull*)(prow + 0);
            a2[1] = *(const ull*)(prow + 2);
            a2[2] = *(const ull*)(prow + 4);
            a2[3] = *(const ull*)(prow + 6);
#pragma unroll
            for (int j = 0; j < 8; j++) {
                float bj = Vs[kk * 64 + tx * 8 + j];
                ull bb = pack2(bj, bj);
                fma2(o2[0][j].u, a2[0], bb);
                fma2(o2[1][j].u, a2[1], bb);
                fma2(o2[2][j].u, a2[2], bb);
                fma2(o2[3][j].u, a2[3], bb);
            }
        }
    }

    // Normalize
#pragma unroll
    for (int p = 0; p < 4; p++) {
        ull inv2 = pack2(1.0f / l_i[2*p], 1.0f / l_i[2*p+1]);
#pragma unroll
        for (int j = 0; j < 8; j++) mul2(o2[p][j].u, inv2);
    }

    // Transpose through smem (O^T[d][row], stride 68) for coalesced stores
    __syncthreads();
#pragma unroll
    for (int j = 0; j < 8; j++)
#pragma unroll
        for (int p = 0; p < 4; p++)
            *(ull*)(Un + (tx * 8 + j) * OT_STRIDE + ty * 8 + 2 * p) = o2[p][j].u;
    __syncthreads();

    const int b = bh >> 3, h = bh & 7;
    float* obase = out + b * (CDIM * SEQ) + (h * HDIM) * SEQ + q0;
#pragma unroll
    for (int it = 0; it < 16; it++) {
        const int id = tid + it * 64;
        const int d  = id >> 4;
        const int r0 = (id & 15) << 2;
        float4 v = *(const float4*)(Un + d * OT_STRIDE + r0);
        *(float4*)(obase + d * SEQ + r0) = v;
    }
}

// ---------------------------------------------------------------------------
extern "C" void kernel_launch(void* const* d_in, const int* in_sizes, int n_in,
                              void* d_out, int out_size)
{
    const float* q_in  = (const float*)d_in[0];   // query     [8,512,32,32]
    const float* kv_in = (const float*)d_in[1];   // key_value [8,512,32,32]
    const float* W     = (const float*)d_in[2];   // W_qkv     [512,1536]
    const float* bias  = (const float*)d_in[3];   // b_qkv     [1536]
    float* out = (float*)d_out;

    cudaFuncSetAttribute(attn_kernel,
                         cudaFuncAttributeMaxDynamicSharedMemorySize,
                         ATTN_SMEM_FLOATS * (int)sizeof(float));

    proj_kernel<<<dim3(4, 64, 3), 256>>>(q_in, kv_in, W, bias);
    attn_kernel<<<dim3(16, 64), 64, ATTN_SMEM_FLOATS * sizeof(float)>>>(out);
}

// round 14
// speedup vs baseline: 1.0733x; 1.0733x over previous
#include <cuda_runtime.h>

// Problem constants
#define BATCH   8
#define CDIM    512
#define SEQ     1024      // H*W = 32*32
#define NHEADS  8
#define HDIM    64
#define SCALE   0.125f    // 1/sqrt(64)
#define LOG2E   1.44269504088896340736f

typedef unsigned long long ull;
union F2 { ull u; float2 f; };

__device__ __forceinline__ ull pack2(float lo, float hi) {
    ull r; asm("mov.b64 %0, {%1, %2};" : "=l"(r) : "f"(lo), "f"(hi)); return r;
}
__device__ __forceinline__ void fma2(ull &d, ull a, ull b) {
    asm("fma.rn.f32x2 %0, %1, %2, %0;" : "+l"(d) : "l"(a), "l"(b));
}
__device__ __forceinline__ void mul2(ull &d, ull a) {
    asm("mul.rn.f32x2 %0, %1, %2;" : "=l"(d) : "l"(d), "l"(a));
}
__device__ __forceinline__ float ex2(float x) {
    float r; asm("ex2.approx.f32 %0, %1;" : "=f"(r) : "f"(x)); return r;
}

// Scratch for projected Q, K, V in [b][h][s][d] layout (fp32). 16 MB each.
__device__ float g_Q[BATCH * CDIM * SEQ];
__device__ float g_K[BATCH * CDIM * SEQ];
__device__ float g_V[BATCH * CDIM * SEQ];

// ---------------------------------------------------------------------------
// Projection GEMM, double-buffered smem pipeline.
//   BM=128, BN=128, BK=16, 256 threads, 8x8 micro-tile, f32x2 FMAs.
//   Per stage: STS -> sync -> prefetch next LDG -> compute. Global latency
//   overlaps the ~700-cycle compute of the current stage.
// ---------------------------------------------------------------------------
__global__ void __launch_bounds__(256, 2)
proj_kernel(const float* __restrict__ q_in,
            const float* __restrict__ kv_in,
            const float* __restrict__ W,
            const float* __restrict__ bias)
{
    __shared__ float As[2][16][128];
    __shared__ float Bs[2][16][128];

    const int proj = blockIdx.z;                   // 0=Q, 1=K, 2=V
    const float* src = (proj == 0) ? q_in : kv_in;
    float* dst = (proj == 0) ? g_Q : ((proj == 1) ? g_K : g_V);

    const int tid = threadIdx.x;
    const int tx  = tid & 15;        // n direction (8 cols each)
    const int ty  = tid >> 4;        // m direction (8 rows each)

    const int b  = blockIdx.y >> 3;
    const int s0 = (blockIdx.y & 7) << 7;
    const int n0 = blockIdx.x << 7;

    const float* Abase = src + b * (CDIM * SEQ) + s0;
    const float* Bbase = W + proj * 512 + n0;

    const int ka = tid >> 5;             // 0..7
    const int ma = (tid & 31) << 2;      // 0..124

    F2 acc2[8][4];                       // [row][col-pair]
#pragma unroll
    for (int i = 0; i < 8; i++)
#pragma unroll
        for (int j = 0; j < 4; j++) acc2[i][j].u = 0ull;

    // preload stage 0
    float4 av0 = *(const float4*)(Abase + ka * SEQ + ma);
    float4 av1 = *(const float4*)(Abase + (ka + 8) * SEQ + ma);
    float4 bv0 = *(const float4*)(Bbase + ka * (3 * CDIM) + ma);
    float4 bv1 = *(const float4*)(Bbase + (ka + 8) * (3 * CDIM) + ma);

    int buf = 0;
    for (int k0 = 0; k0 < CDIM; k0 += 16, buf ^= 1) {
        *(float4*)&As[buf][ka][ma]     = av0;
        *(float4*)&As[buf][ka + 8][ma] = av1;
        *(float4*)&Bs[buf][ka][ma]     = bv0;
        *(float4*)&Bs[buf][ka + 8][ma] = bv1;
        __syncthreads();

        if (k0 + 16 < CDIM) {           // prefetch next stage (overlaps compute)
            av0 = *(const float4*)(Abase + (k0 + 16 + ka) * SEQ + ma);
            av1 = *(const float4*)(Abase + (k0 + 24 + ka) * SEQ + ma);
            bv0 = *(const float4*)(Bbase + (k0 + 16 + ka) * (3 * CDIM) + ma);
            bv1 = *(const float4*)(Bbase + (k0 + 24 + ka) * (3 * CDIM) + ma);
        }

#pragma unroll
        for (int kk = 0; kk < 16; kk++) {
            ulonglong2 b01 = *(const ulonglong2*)&Bs[buf][kk][tx * 8];
            ulonglong2 b23 = *(const ulonglong2*)&Bs[buf][kk][tx * 8 + 4];
            ull b2[4] = { b01.x, b01.y, b23.x, b23.y };
            float4 a0 = *(const float4*)&As[buf][kk][ty * 8];
            float4 a1 = *(const float4*)&As[buf][kk][ty * 8 + 4];
            ull as_[8] = { pack2(a0.x, a0.x), pack2(a0.y, a0.y),
                           pack2(a0.z, a0.z), pack2(a0.w, a0.w),
                           pack2(a1.x, a1.x), pack2(a1.y, a1.y),
                           pack2(a1.z, a1.z), pack2(a1.w, a1.w) };
#pragma unroll
            for (int i = 0; i < 8; i++)
#pragma unroll
                for (int j = 0; j < 4; j++)
                    fma2(acc2[i][j].u, as_[i], b2[j]);
        }
    }

    // epilogue: add bias, write to [b][h][s][d]
    const int nbase = n0 + tx * 8;           // multiple of 8 -> one head
    const int h  = nbase >> 6;
    const int d0 = nbase & 63;
    float bv[8];
#pragma unroll
    for (int j = 0; j < 8; j++) bv[j] = bias[proj * 512 + nbase + j];

    float* obase = dst + b * (CDIM * SEQ) + h * (SEQ * HDIM) + d0;
#pragma unroll
    for (int i = 0; i < 8; i++) {
        const int s = s0 + ty * 8 + i;
        float4 v0, v1;
        v0.x = acc2[i][0].f.x + bv[0]; v0.y = acc2[i][0].f.y + bv[1];
        v0.z = acc2[i][1].f.x + bv[2]; v0.w = acc2[i][1].f.y + bv[3];
        v1.x = acc2[i][2].f.x + bv[4]; v1.y = acc2[i][2].f.y + bv[5];
        v1.z = acc2[i][3].f.x + bv[6]; v1.w = acc2[i][3].f.y + bv[7];
        *(float4*)(obase + s * HDIM + 0) = v0;
        *(float4*)(obase + s * HDIM + 4) = v1;
    }
}

// ---------------------------------------------------------------------------
// Flash attention: 128 threads, 64x64 tiles, 8x4 per-thread micro-tile,
// f32x2-packed accumulators over q-row pairs. Softmax in exp2 domain.
//
// K tile is stored XOR-swizzled: element (key, d) lives at
//   Un[key*64 + (d ^ ((key>>2) & 15))]
// so the S-GEMM column read (fixed d=kk, keys 4*tx+j) hits bank (kk^tx)&31
// -> 16 distinct banks over the 16 tx lanes -> conflict-free, and the XOR
// index kk^tx is shared by all four j loads.
//
// Dynamic smem (floats):
//   Qt [64][64]  Q^T [d][row], pre-scaled              (4096)
//   Un [64][68]  union: K swizzled (64*64) / P^T stride 66 / O^T stride 68
//   Vs [64][64]  V [key][d]                            (4096)
// Total 50,176 B -> 4 blocks/SM.
// ---------------------------------------------------------------------------
#define PT_STRIDE 66
#define OT_STRIDE 68
#define QT_F (64 * 64)
#define U_F  (64 * OT_STRIDE)
#define VS_F (64 * 64)
#define ATTN_SMEM_FLOATS (QT_F + U_F + VS_F)

__global__ void __launch_bounds__(128)
attn_kernel(float* __restrict__ out)
{
    extern __shared__ float sm[];
    float* Qt = sm;                 // [d][row], stride 64
    float* Un = sm + QT_F;          // K swizzled / Pt(66) / Ot(68)
    float* Vs = sm + QT_F + U_F;    // [key][d], stride 64

    const int tid = threadIdx.x;
    const int tx  = tid & 15;       // 4 keys / 4 d-cols
    const int ty  = tid >> 4;       // 0..7 -> 8 q-rows (ty*8 ..)

    const int bh = blockIdx.y;
    const int q0 = blockIdx.x << 6;
    const float* Qp = g_Q + bh * (SEQ * HDIM);
    const float* Kp = g_K + bh * (SEQ * HDIM);
    const float* Vp = g_V + bh * (SEQ * HDIM);

    const float qscale = SCALE * LOG2E;

    // Load Q tile transposed, pre-scaled
#pragma unroll
    for (int it = 0; it < 4; it++) {
        const int id  = tid + it * 128 * 2;   // use 2 rounds of 256? keep simple
        (void)id;
    }
#pragma unroll
    for (int it = 0; it < 8; it++) {
        const int id  = tid + it * 128;
        const int row = id >> 4;
        const int d0  = (id & 15) << 2;
        float4 qv = *(const float4*)(Qp + (q0 + row) * HDIM + d0);
        Qt[(d0 + 0) * 64 + row] = qv.x * qscale;
        Qt[(d0 + 1) * 64 + row] = qv.y * qscale;
        Qt[(d0 + 2) * 64 + row] = qv.z * qscale;
        Qt[(d0 + 3) * 64 + row] = qv.w * qscale;
    }

    F2 o2[4][4];                    // [row-pair][d-col]
    float m_i[8], l_i[8];
#pragma unroll
    for (int p = 0; p < 4; p++)
#pragma unroll
        for (int j = 0; j < 4; j++) o2[p][j].u = 0ull;
#pragma unroll
    for (int i = 0; i < 8; i++) { m_i[i] = -1e30f; l_i[i] = 0.0f; }

    // Per-thread K read bases (swizzled tile): key rows 4*tx + j
    const float* KsB0 = Un + (tx * 4 + 0) * 64;
    const float* KsB1 = Un + (tx * 4 + 1) * 64;
    const float* KsB2 = Un + (tx * 4 + 2) * 64;
    const float* KsB3 = Un + (tx * 4 + 3) * 64;

    for (int kt = 0; kt < 16; kt++) {
        const int key0 = kt << 6;
        __syncthreads();            // prev PV done reading Un(Pt)/Vs

        // Load K tile (XOR-swizzled) and V tile
#pragma unroll
        for (int it = 0; it < 8; it++) {
            const int id   = tid + it * 128;
            const int krow = id >> 4;
            const int d0   = (id & 15) << 2;
            const int g    = (krow >> 2) & 15;
            float4 kv = *(const float4*)(Kp + (key0 + krow) * HDIM + d0);
            Un[krow * 64 + ((d0 + 0) ^ g)] = kv.x;
            Un[krow * 64 + ((d0 + 1) ^ g)] = kv.y;
            Un[krow * 64 + ((d0 + 2) ^ g)] = kv.z;
            Un[krow * 64 + ((d0 + 3) ^ g)] = kv.w;
            float4 vv = *(const float4*)(Vp + (key0 + krow) * HDIM + d0);
            *(float4*)&Vs[krow * 64 + d0] = vv;
        }
        __syncthreads();

        // ---- S = Q*K^T (log2 domain), 8 rows x 4 keys, packed over rows ----
        F2 s2[4][4];
#pragma unroll
        for (int p = 0; p < 4; p++)
#pragma unroll
            for (int j = 0; j < 4; j++) s2[p][j].u = 0ull;

#pragma unroll 8
        for (int kk = 0; kk < 64; kk++) {
            ulonglong2 a01 = *(const ulonglong2*)(Qt + kk * 64 + ty * 8);
            ulonglong2 a23 = *(const ulonglong2*)(Qt + kk * 64 + ty * 8 + 4);
            const int idx = kk ^ tx;         // conflict-free swizzled index
            float bb0 = KsB0[idx];
            float bb1 = KsB1[idx];
            float bb2 = KsB2[idx];
            float bb3 = KsB3[idx];
            ull b2[4] = { pack2(bb0, bb0), pack2(bb1, bb1),
                          pack2(bb2, bb2), pack2(bb3, bb3) };
            ull a2[4] = { a01.x, a01.y, a23.x, a23.y };
#pragma unroll
            for (int p = 0; p < 4; p++)
#pragma unroll
                for (int j = 0; j < 4; j++)
                    fma2(s2[p][j].u, a2[p], b2[j]);
        }

        // ---- Online softmax (exp2 domain), rows i = 2p + half ----
        float rm[8], rs[8], alpha[8];
#pragma unroll
        for (int p = 0; p < 4; p++) {
            rm[2*p]   = fmaxf(fmaxf(s2[p][0].f.x, s2[p][1].f.x),
                              fmaxf(s2[p][2].f.x, s2[p][3].f.x));
            rm[2*p+1] = fmaxf(fmaxf(s2[p][0].f.y, s2[p][1].f.y),
                              fmaxf(s2[p][2].f.y, s2[p][3].f.y));
        }
#pragma unroll
        for (int msk = 1; msk < 16; msk <<= 1)
#pragma unroll
            for (int i = 0; i < 8; i++)
                rm[i] = fmaxf(rm[i], __shfl_xor_sync(0xffffffffu, rm[i], msk));

#pragma unroll
        for (int i = 0; i < 8; i++) {
            float mn = fmaxf(m_i[i], rm[i]);
            alpha[i] = ex2(m_i[i] - mn);
            m_i[i] = mn;
        }
#pragma unroll
        for (int p = 0; p < 4; p++) {
#pragma unroll
            for (int j = 0; j < 4; j++) {
                s2[p][j].f.x = ex2(s2[p][j].f.x - m_i[2*p]);
                s2[p][j].f.y = ex2(s2[p][j].f.y - m_i[2*p+1]);
            }
            rs[2*p]   = s2[p][0].f.x + s2[p][1].f.x + s2[p][2].f.x + s2[p][3].f.x;
            rs[2*p+1] = s2[p][0].f.y + s2[p][1].f.y + s2[p][2].f.y + s2[p][3].f.y;
        }
#pragma unroll
        for (int msk = 1; msk < 16; msk <<= 1)
#pragma unroll
            for (int i = 0; i < 8; i++)
                rs[i] += __shfl_xor_sync(0xffffffffu, rs[i], msk);
#pragma unroll
        for (int i = 0; i < 8; i++)
            l_i[i] = l_i[i] * alpha[i] + rs[i];
#pragma unroll
        for (int p = 0; p < 4; p++) {
            ull a2p = pack2(alpha[2*p], alpha[2*p+1]);
#pragma unroll
            for (int j = 0; j < 4; j++) mul2(o2[p][j].u, a2p);
        }

        __syncthreads();            // everyone done reading K from Un
        // Stage P^T[key][row] (stride 66, 8B-aligned ull stores)
#pragma unroll
        for (int j = 0; j < 4; j++)
#pragma unroll
            for (int p = 0; p < 4; p++)
                *(ull*)(Un + (tx * 4 + j) * PT_STRIDE + ty * 8 + 2 * p) = s2[p][j].u;
        __syncthreads();

        // ---- O += P*V, packed over rows (a pairs free from P^T) ----
#pragma unroll 8
        for (int kk = 0; kk < 64; kk++) {
            const float* prow = Un + kk * PT_STRIDE + ty * 8;
            ull a2[4];
            a2[0] = *(const ull*)(prow + 0);
            a2[1] = *(const ull*)(prow + 2);
            a2[2] = *(const ull*)(prow + 4);
            a2[3] = *(const ull*)(prow + 6);
            float4 v = *(const float4*)(Vs + kk * 64 + tx * 4);
            ull b2[4] = { pack2(v.x, v.x), pack2(v.y, v.y),
                          pack2(v.z, v.z), pack2(v.w, v.w) };
#pragma unroll
            for (int p = 0; p < 4; p++)
#pragma unroll
                for (int j = 0; j < 4; j++)
                    fma2(o2[p][j].u, a2[p], b2[j]);
        }
    }

    // Normalize
#pragma unroll
    for (int p = 0; p < 4; p++) {
        ull inv2 = pack2(1.0f / l_i[2*p], 1.0f / l_i[2*p+1]);
#pragma unroll
        for (int j = 0; j < 4; j++) mul2(o2[p][j].u, inv2);
    }

    // Transpose through smem (O^T[d][row], stride 68) for coalesced stores
    __syncthreads();
#pragma unroll
    for (int j = 0; j < 4; j++)
#pragma unroll
        for (int p = 0; p < 4; p++)
            *(ull*)(Un + (tx * 4 + j) * OT_STRIDE + ty * 8 + 2 * p) = o2[p][j].u;
    __syncthreads();

    const int b = bh >> 3, h = bh & 7;
    float* obase = out + b * (CDIM * SEQ) + (h * HDIM) * SEQ + q0;
#pragma unroll
    for (int it = 0; it < 8; it++) {
        const int id = tid + it * 128;
        const int d  = id >> 4;
        const int r0 = (id & 15) << 2;
        float4 v = *(const float4*)(Un + d * OT_STRIDE + r0);
        *(float4*)(obase + d * SEQ + r0) = v;
    }
}

// ---------------------------------------------------------------------------
extern "C" void kernel_launch(void* const* d_in, const int* in_sizes, int n_in,
                              void* d_out, int out_size)
{
    const float* q_in  = (const float*)d_in[0];   // query     [8,512,32,32]
    const float* kv_in = (const float*)d_in[1];   // key_value [8,512,32,32]
    const float* W     = (const float*)d_in[2];   // W_qkv     [512,1536]
    const float* bias  = (const float*)d_in[3];   // b_qkv     [1536]
    float* out = (float*)d_out;

    cudaFuncSetAttribute(attn_kernel,
                         cudaFuncAttributeMaxDynamicSharedMemorySize,
                         ATTN_SMEM_FLOATS * (int)sizeof(float));

    proj_kernel<<<dim3(4, 64, 3), 256>>>(q_in, kv_in, W, bias);
    attn_kernel<<<dim3(16, 64), 128, ATTN_SMEM_FLOATS * sizeof(float)>>>(out);
}

// round 15
// speedup vs baseline: 1.2412x; 1.1564x over previous
#include <cuda_runtime.h>

// Problem constants
#define BATCH   8
#define CDIM    512
#define SEQ     1024      // H*W = 32*32
#define NHEADS  8
#define HDIM    64
#define SCALE   0.125f    // 1/sqrt(64)
#define LOG2E   1.44269504088896340736f

typedef unsigned long long ull;
union F2 { ull u; float2 f; };

__device__ __forceinline__ ull pack2(float lo, float hi) {
    ull r; asm("mov.b64 %0, {%1, %2};" : "=l"(r) : "f"(lo), "f"(hi)); return r;
}
__device__ __forceinline__ void fma2(ull &d, ull a, ull b) {
    asm("fma.rn.f32x2 %0, %1, %2, %0;" : "+l"(d) : "l"(a), "l"(b));
}
__device__ __forceinline__ void mul2(ull &d, ull a) {
    asm("mul.rn.f32x2 %0, %1, %2;" : "=l"(d) : "l"(d), "l"(a));
}
__device__ __forceinline__ float ex2(float x) {
    float r; asm("ex2.approx.f32 %0, %1;" : "=f"(r) : "f"(x)); return r;
}

// tf32 split: x ~= hi + lo, each representable in tf32 (11-bit mantissa).
__device__ __forceinline__ void tf32_split(float x, unsigned &h, unsigned &l) {
    asm("cvt.rna.tf32.f32 %0, %1;" : "=r"(h) : "f"(x));
    float r = x - __uint_as_float(h);
    asm("cvt.rna.tf32.f32 %0, %1;" : "=r"(l) : "f"(r));
}

__device__ __forceinline__ void mma_tf32(float* c, const unsigned* a, const unsigned* b) {
    asm volatile(
        "mma.sync.aligned.m16n8k8.row.col.f32.tf32.tf32.f32 "
        "{%0,%1,%2,%3}, {%4,%5,%6,%7}, {%8,%9}, {%0,%1,%2,%3};"
        : "+f"(c[0]), "+f"(c[1]), "+f"(c[2]), "+f"(c[3])
        : "r"(a[0]), "r"(a[1]), "r"(a[2]), "r"(a[3]), "r"(b[0]), "r"(b[1]));
}

// Scratch for projected Q, K, V in [b][h][s][d] layout (fp32). 16 MB each.
__device__ float g_Q[BATCH * CDIM * SEQ];
__device__ float g_K[BATCH * CDIM * SEQ];
__device__ float g_V[BATCH * CDIM * SEQ];

// ---------------------------------------------------------------------------
// Projection GEMM on tensor cores (3xTF32 mma.sync, ~fp32 accuracy).
//   C[m][n] = sum_k A[m][k] * W[k][n],  m = b*1024 + s, n in [0,1536)
//   A[m][k] = src[b][k][s]  (NCHW => As[k][m] copy is fully coalesced)
//   Block: 256 thr (8 warps), tile M=128 x N=128, K-stage 16, double-buffered.
//   Warp tile 64x32 (warps 2x4); per warp 4x4 m16n8k8 frags x 2 ksteps.
//   Smem stride 136 => fragment gathers bank-conflict-free (8*t4+g perm).
// ---------------------------------------------------------------------------
#define PJ_STRIDE 136
#define PJ_ARR    (16 * PJ_STRIDE)          // 2176 words per array
#define PJ_BUF    (4 * PJ_ARR)              // Ah, Al, Bh, Bl
#define PJ_SMEM_WORDS (2 * PJ_BUF)          // double buffer: 69,632 B

__global__ void __launch_bounds__(256)
proj_mma_kernel(const float* __restrict__ q_in,
                const float* __restrict__ kv_in,
                const float* __restrict__ W,
                const float* __restrict__ bias)
{
    extern __shared__ unsigned psm[];

    const int nb = blockIdx.x;                 // 0..11  (n tiles of 128)
    const int mb = blockIdx.y;                 // 0..63  (m tiles of 128)
    const int proj = nb >> 2;                  // 4 n-tiles per projection
    const float* src = (proj == 0) ? q_in : kv_in;
    float* dst = (proj == 0) ? g_Q : ((proj == 1) ? g_K : g_V);

    const int tid  = threadIdx.x;
    const int lane = tid & 31;
    const int warp = tid >> 5;
    const int g    = lane >> 2;                // 0..7
    const int t4   = lane & 3;                 // 0..3

    const int warp_m = (warp >> 2) * 64;       // 0 or 64
    const int warp_n = (warp & 3) * 32;        // 0,32,64,96

    const int b  = mb >> 3;
    const int s0 = (mb & 7) << 7;
    const int n0 = nb << 7;                    // global n (0..1535)

    const float* Abase = src + b * (CDIM * SEQ) + s0;   // + k*SEQ + m
    const float* Bbase = W + n0;                        // + k*1536 + n

    const int ka = tid >> 5;                   // 0..7
    const int ma = (tid & 31) << 2;            // 0..124

    float c[4][4][4];                          // [mt][nt][reg]
#pragma unroll
    for (int mt = 0; mt < 4; mt++)
#pragma unroll
        for (int nt = 0; nt < 4; nt++)
#pragma unroll
            for (int r = 0; r < 4; r++) c[mt][nt][r] = 0.0f;

    // preload stage 0
    float4 av0 = *(const float4*)(Abase + ka * SEQ + ma);
    float4 av1 = *(const float4*)(Abase + (ka + 8) * SEQ + ma);
    float4 bv0 = *(const float4*)(Bbase + ka * (3 * CDIM) + ma);
    float4 bv1 = *(const float4*)(Bbase + (ka + 8) * (3 * CDIM) + ma);

    int buf = 0;
    for (int k0 = 0; k0 < CDIM; k0 += 16, buf ^= 1) {
        unsigned* Ah = psm + buf * PJ_BUF;
        unsigned* Al = Ah + PJ_ARR;
        unsigned* Bh = Al + PJ_ARR;
        unsigned* Bl = Bh + PJ_ARR;

        // convert to tf32 hi/lo and store both K-rows of A and B
        {
            uint4 h, l;
            tf32_split(av0.x, h.x, l.x); tf32_split(av0.y, h.y, l.y);
            tf32_split(av0.z, h.z, l.z); tf32_split(av0.w, h.w, l.w);
            *(uint4*)&Ah[ka * PJ_STRIDE + ma] = h;
            *(uint4*)&Al[ka * PJ_STRIDE + ma] = l;
            tf32_split(av1.x, h.x, l.x); tf32_split(av1.y, h.y, l.y);
            tf32_split(av1.z, h.z, l.z); tf32_split(av1.w, h.w, l.w);
            *(uint4*)&Ah[(ka + 8) * PJ_STRIDE + ma] = h;
            *(uint4*)&Al[(ka + 8) * PJ_STRIDE + ma] = l;
            tf32_split(bv0.x, h.x, l.x); tf32_split(bv0.y, h.y, l.y);
            tf32_split(bv0.z, h.z, l.z); tf32_split(bv0.w, h.w, l.w);
            *(uint4*)&Bh[ka * PJ_STRIDE + ma] = h;
            *(uint4*)&Bl[ka * PJ_STRIDE + ma] = l;
            tf32_split(bv1.x, h.x, l.x); tf32_split(bv1.y, h.y, l.y);
            tf32_split(bv1.z, h.z, l.z); tf32_split(bv1.w, h.w, l.w);
            *(uint4*)&Bh[(ka + 8) * PJ_STRIDE + ma] = h;
            *(uint4*)&Bl[(ka + 8) * PJ_STRIDE + ma] = l;
        }
        __syncthreads();

        if (k0 + 16 < CDIM) {                  // prefetch next stage
            av0 = *(const float4*)(Abase + (k0 + 16 + ka) * SEQ + ma);
            av1 = *(const float4*)(Abase + (k0 + 24 + ka) * SEQ + ma);
            bv0 = *(const float4*)(Bbase + (k0 + 16 + ka) * (3 * CDIM) + ma);
            bv1 = *(const float4*)(Bbase + (k0 + 24 + ka) * (3 * CDIM) + ma);
        }

#pragma unroll
        for (int ks = 0; ks < 2; ks++) {
            const int kb = ks * 8;
            // B fragments: b0 = B[k=t4][n=col], b1 = B[k=t4+4][n=col]
            unsigned bh[4][2], bl[4][2];
            const int bcol = warp_n + g;
#pragma unroll
            for (int nt = 0; nt < 4; nt++) {
                bh[nt][0] = Bh[(kb + t4) * PJ_STRIDE + bcol + nt * 8];
                bh[nt][1] = Bh[(kb + t4 + 4) * PJ_STRIDE + bcol + nt * 8];
                bl[nt][0] = Bl[(kb + t4) * PJ_STRIDE + bcol + nt * 8];
                bl[nt][1] = Bl[(kb + t4 + 4) * PJ_STRIDE + bcol + nt * 8];
            }
            const int arow = warp_m + g;
#pragma unroll
            for (int mt = 0; mt < 4; mt++) {
                // a0=(g,t4) a1=(g+8,t4) a2=(g,t4+4) a3=(g+8,t4+4), A[m][k]=As[k][m]
                unsigned ah[4], al[4];
                ah[0] = Ah[(kb + t4) * PJ_STRIDE + arow + mt * 16];
                ah[1] = Ah[(kb + t4) * PJ_STRIDE + arow + mt * 16 + 8];
                ah[2] = Ah[(kb + t4 + 4) * PJ_STRIDE + arow + mt * 16];
                ah[3] = Ah[(kb + t4 + 4) * PJ_STRIDE + arow + mt * 16 + 8];
                al[0] = Al[(kb + t4) * PJ_STRIDE + arow + mt * 16];
                al[1] = Al[(kb + t4) * PJ_STRIDE + arow + mt * 16 + 8];
                al[2] = Al[(kb + t4 + 4) * PJ_STRIDE + arow + mt * 16];
                al[3] = Al[(kb + t4 + 4) * PJ_STRIDE + arow + mt * 16 + 8];
#pragma unroll
                for (int nt = 0; nt < 4; nt++) {
                    mma_tf32(c[mt][nt], ah, bh[nt]);   // hi*hi
                    mma_tf32(c[mt][nt], ah, bl[nt]);   // hi*lo
                    mma_tf32(c[mt][nt], al, bh[nt]);   // lo*hi
                }
            }
        }
        __syncthreads();
    }

    // Epilogue: c0=(g, 2t4), c1=(g, 2t4+1), c2=(g+8, 2t4), c3=(g+8, 2t4+1)
#pragma unroll
    for (int nt = 0; nt < 4; nt++) {
        const int n_g = n0 + warp_n + nt * 8 + 2 * t4;
        const int nn  = n_g & 511;
        const int h   = nn >> 6, d = nn & 63;
        const float bx = bias[n_g], by = bias[n_g + 1];
        float* op = dst + b * (CDIM * SEQ) + h * (SEQ * HDIM) + d;
#pragma unroll
        for (int mt = 0; mt < 4; mt++) {
            const int srow = s0 + warp_m + mt * 16 + g;
            float2 v0 = { c[mt][nt][0] + bx, c[mt][nt][1] + by };
            float2 v1 = { c[mt][nt][2] + bx, c[mt][nt][3] + by };
            *(float2*)(op + srow * HDIM)       = v0;
            *(float2*)(op + (srow + 8) * HDIM) = v1;
        }
    }
}

// ---------------------------------------------------------------------------
// Flash attention (round-6 version, best measured 385.8us): 128 threads,
// 64x64 tiles, 8x4 per-thread micro-tile, f32x2-packed accumulators over
// q-row pairs. Softmax in exp2 domain.
// Dynamic smem (floats):
//   Qt  [64][64]  Q^T tile [d][row], pre-scaled          (4096)
//   Ks  [64][65]  K tile [key][d]; reused as P^T stride 68 and O^T stride 68
//   Vs  [64][64]  V tile [key][d]                        (4096)
// ---------------------------------------------------------------------------
#define ATTN_SMEM_FLOATS (4096 + 4352 + 4096)

__global__ void __launch_bounds__(128)
attn_kernel(float* __restrict__ out)
{
    extern __shared__ float sm[];
    float* Qt = sm;                 // [d][row], stride 64
    float* Ks = sm + 4096;          // [key][d] stride 65 / P^T,O^T stride 68
    float* Vs = sm + 8448;          // [key][d] stride 64

    const int tid = threadIdx.x;
    const int tx  = tid & 15;       // 4 keys / 4 d-cols
    const int ty  = tid >> 4;       // 0..7 -> 8 q-rows (ty*8 ..)

    const int bh = blockIdx.y;
    const int q0 = blockIdx.x << 6;
    const float* Qp = g_Q + bh * (SEQ * HDIM);
    const float* Kp = g_K + bh * (SEQ * HDIM);
    const float* Vp = g_V + bh * (SEQ * HDIM);

    const float qscale = SCALE * LOG2E;

    // Load Q tile transposed, pre-scaled
#pragma unroll
    for (int it = 0; it < 8; it++) {
        const int id  = tid + it * 128;
        const int row = id >> 4;
        const int d0  = (id & 15) << 2;
        float4 qv = *(const float4*)(Qp + (q0 + row) * HDIM + d0);
        Qt[(d0 + 0) * 64 + row] = qv.x * qscale;
        Qt[(d0 + 1) * 64 + row] = qv.y * qscale;
        Qt[(d0 + 2) * 64 + row] = qv.z * qscale;
        Qt[(d0 + 3) * 64 + row] = qv.w * qscale;
    }

    F2 o2[4][4];                    // [row-pair][d-col]
    float m_i[8], l_i[8];
#pragma unroll
    for (int p = 0; p < 4; p++)
#pragma unroll
        for (int j = 0; j < 4; j++) o2[p][j].u = 0ull;
#pragma unroll
    for (int i = 0; i < 8; i++) { m_i[i] = -1e30f; l_i[i] = 0.0f; }

    for (int kt = 0; kt < 16; kt++) {
        const int key0 = kt << 6;
        __syncthreads();            // prev PV done reading Ks(Pt)/Vs

        // Load K (stride 65, scalar stores) and V tiles
#pragma unroll
        for (int it = 0; it < 8; it++) {
            const int id   = tid + it * 128;
            const int krow = id >> 4;
            const int d0   = (id & 15) << 2;
            float4 kv = *(const float4*)(Kp + (key0 + krow) * HDIM + d0);
            Ks[krow * 65 + d0 + 0] = kv.x;
            Ks[krow * 65 + d0 + 1] = kv.y;
            Ks[krow * 65 + d0 + 2] = kv.z;
            Ks[krow * 65 + d0 + 3] = kv.w;
            float4 vv = *(const float4*)(Vp + (key0 + krow) * HDIM + d0);
            *(float4*)&Vs[krow * 64 + d0] = vv;
        }
        __syncthreads();

        // ---- S = Q*K^T (log2 domain), 8 rows x 4 keys, packed over rows ----
        F2 s2[4][4];
#pragma unroll
        for (int p = 0; p < 4; p++)
#pragma unroll
            for (int j = 0; j < 4; j++) s2[p][j].u = 0ull;

#pragma unroll 8
        for (int kk = 0; kk < 64; kk++) {
            ulonglong2 a01 = *(const ulonglong2*)(Qt + kk * 64 + ty * 8);
            ulonglong2 a23 = *(const ulonglong2*)(Qt + kk * 64 + ty * 8 + 4);
            float bb0 = Ks[(tx * 4 + 0) * 65 + kk];
            float bb1 = Ks[(tx * 4 + 1) * 65 + kk];
            float bb2 = Ks[(tx * 4 + 2) * 65 + kk];
            float bb3 = Ks[(tx * 4 + 3) * 65 + kk];
            ull b2[4] = { pack2(bb0, bb0), pack2(bb1, bb1),
                          pack2(bb2, bb2), pack2(bb3, bb3) };
            ull a2[4] = { a01.x, a01.y, a23.x, a23.y };
#pragma unroll
            for (int p = 0; p < 4; p++)
#pragma unroll
                for (int j = 0; j < 4; j++)
                    fma2(s2[p][j].u, a2[p], b2[j]);
        }

        // ---- Online softmax (exp2 domain) ----
        float rm[8], rs[8], alpha[8];
#pragma unroll
        for (int p = 0; p < 4; p++) {
            rm[2*p]   = fmaxf(fmaxf(s2[p][0].f.x, s2[p][1].f.x),
                              fmaxf(s2[p][2].f.x, s2[p][3].f.x));
            rm[2*p+1] = fmaxf(fmaxf(s2[p][0].f.y, s2[p][1].f.y),
                              fmaxf(s2[p][2].f.y, s2[p][3].f.y));
        }
#pragma unroll
        for (int msk = 1; msk < 16; msk <<= 1)
#pragma unroll
            for (int i = 0; i < 8; i++)
                rm[i] = fmaxf(rm[i], __shfl_xor_sync(0xffffffffu, rm[i], msk));

#pragma unroll
        for (int i = 0; i < 8; i++) {
            float mn = fmaxf(m_i[i], rm[i]);
            alpha[i] = ex2(m_i[i] - mn);
            m_i[i] = mn;
        }
#pragma unroll
        for (int p = 0; p < 4; p++) {
#pragma unroll
            for (int j = 0; j < 4; j++) {
                s2[p][j].f.x = ex2(s2[p][j].f.x - m_i[2*p]);
                s2[p][j].f.y = ex2(s2[p][j].f.y - m_i[2*p+1]);
            }
            rs[2*p]   = s2[p][0].f.x + s2[p][1].f.x + s2[p][2].f.x + s2[p][3].f.x;
            rs[2*p+1] = s2[p][0].f.y + s2[p][1].f.y + s2[p][2].f.y + s2[p][3].f.y;
        }
#pragma unroll
        for (int msk = 1; msk < 16; msk <<= 1)
#pragma unroll
            for (int i = 0; i < 8; i++)
                rs[i] += __shfl_xor_sync(0xffffffffu, rs[i], msk);
#pragma unroll
        for (int i = 0; i < 8; i++)
            l_i[i] = l_i[i] * alpha[i] + rs[i];
#pragma unroll
        for (int p = 0; p < 4; p++) {
            ull a2p = pack2(alpha[2*p], alpha[2*p+1]);
#pragma unroll
            for (int j = 0; j < 4; j++) mul2(o2[p][j].u, a2p);
        }

        __syncthreads();            // everyone done reading K from Ks
        // Stage P^T[key][row] with stride 68 (16B-aligned rows), 64-bit stores
#pragma unroll
        for (int j = 0; j < 4; j++)
#pragma unroll
            for (int p = 0; p < 4; p++)
                *(ull*)(Ks + (tx * 4 + j) * 68 + ty * 8 + 2 * p) = s2[p][j].u;
        __syncthreads();

        // ---- O += P*V, packed over rows (a pairs free from P^T) ----
#pragma unroll 8
        for (int kk = 0; kk < 64; kk++) {
            ulonglong2 a01 = *(const ulonglong2*)(Ks + kk * 68 + ty * 8);
            ulonglong2 a23 = *(const ulonglong2*)(Ks + kk * 68 + ty * 8 + 4);
            float4 v = *(const float4*)(Vs + kk * 64 + tx * 4);
            ull b2[4] = { pack2(v.x, v.x), pack2(v.y, v.y),
                          pack2(v.z, v.z), pack2(v.w, v.w) };
            ull a2[4] = { a01.x, a01.y, a23.x, a23.y };
#pragma unroll
            for (int p = 0; p < 4; p++)
#pragma unroll
                for (int j = 0; j < 4; j++)
                    fma2(o2[p][j].u, a2[p], b2[j]);
        }
    }

    // Normalize
#pragma unroll
    for (int p = 0; p < 4; p++) {
        ull inv2 = pack2(1.0f / l_i[2*p], 1.0f / l_i[2*p+1]);
#pragma unroll
        for (int j = 0; j < 4; j++) mul2(o2[p][j].u, inv2);
    }

    // Transpose through smem (O^T[d][row], stride 68) for coalesced stores
    __syncthreads();
#pragma unroll
    for (int j = 0; j < 4; j++)
#pragma unroll
        for (int p = 0; p < 4; p++)
            *(ull*)(Ks + (tx * 4 + j) * 68 + ty * 8 + 2 * p) = o2[p][j].u;
    __syncthreads();

    const int b = bh >> 3, h = bh & 7;
    float* obase = out + b * (CDIM * SEQ) + (h * HDIM) * SEQ + q0;
#pragma unroll
    for (int it = 0; it < 8; it++) {
        const int id = tid + it * 128;
        const int d  = id >> 4;
        const int r0 = (id & 15) << 2;
        float4 v = *(const float4*)(Ks + d * 68 + r0);
        *(float4*)(obase + d * SEQ + r0) = v;
    }
}

// ---------------------------------------------------------------------------
extern "C" void kernel_launch(void* const* d_in, const int* in_sizes, int n_in,
                              void* d_out, int out_size)
{
    const float* q_in  = (const float*)d_in[0];   // query     [8,512,32,32]
    const float* kv_in = (const float*)d_in[1];   // key_value [8,512,32,32]
    const float* W     = (const float*)d_in[2];   // W_qkv     [512,1536]
    const float* bias  = (const float*)d_in[3];   // b_qkv     [1536]
    float* out = (float*)d_out;

    cudaFuncSetAttribute(proj_mma_kernel,
                         cudaFuncAttributeMaxDynamicSharedMemorySize,
                         PJ_SMEM_WORDS * (int)sizeof(unsigned));
    cudaFuncSetAttribute(attn_kernel,
                         cudaFuncAttributeMaxDynamicSharedMemorySize,
                         ATTN_SMEM_FLOATS * (int)sizeof(float));

    proj_mma_kernel<<<dim3(12, 64), 256, PJ_SMEM_WORDS * sizeof(unsigned)>>>(
        q_in, kv_in, W, bias);
    attn_kernel<<<dim3(16, 64), 128, ATTN_SMEM_FLOATS * sizeof(float)>>>(out);
}

// round 16
// speedup vs baseline: 1.8649x; 1.5025x over previous
#include <cuda_runtime.h>

// Problem constants
#define BATCH   8
#define CDIM    512
#define SEQ     1024      // H*W = 32*32
#define NHEADS  8
#define HDIM    64
#define SCALE   0.125f    // 1/sqrt(64)
#define LOG2E   1.44269504088896340736f

__device__ __forceinline__ float ex2(float x) {
    float r; asm("ex2.approx.f32 %0, %1;" : "=f"(r) : "f"(x)); return r;
}

// tf32 split (projection): x ~= hi + lo, each tf32.
__device__ __forceinline__ void tf32_split(float x, unsigned &h, unsigned &l) {
    asm("cvt.rna.tf32.f32 %0, %1;" : "=r"(h) : "f"(x));
    float r = x - __uint_as_float(h);
    asm("cvt.rna.tf32.f32 %0, %1;" : "=r"(l) : "f"(r));
}

__device__ __forceinline__ void mma_tf32(float* c, const unsigned* a, const unsigned* b) {
    asm volatile(
        "mma.sync.aligned.m16n8k8.row.col.f32.tf32.tf32.f32 "
        "{%0,%1,%2,%3}, {%4,%5,%6,%7}, {%8,%9}, {%0,%1,%2,%3};"
        : "+f"(c[0]), "+f"(c[1]), "+f"(c[2]), "+f"(c[3])
        : "r"(a[0]), "r"(a[1]), "r"(a[2]), "r"(a[3]), "r"(b[0]), "r"(b[1]));
}

// bf16 helpers (attention): pack two floats into bf16x2 (first elem -> low half)
__device__ __forceinline__ unsigned packbf(float first, float second) {
    unsigned r;
    asm("cvt.rn.bf16x2.f32 %0, %1, %2;" : "=r"(r) : "f"(second), "f"(first));
    return r;
}
// 2-term bf16 split of a pair: h = bf16x2(x,y), l = bf16x2 of residuals
__device__ __forceinline__ void bsplit2(float x, float y, unsigned &h, unsigned &l) {
    h = packbf(x, y);
    float rx = x - __uint_as_float(h << 16);
    float ry = y - __uint_as_float(h & 0xffff0000u);
    l = packbf(rx, ry);
}

__device__ __forceinline__ void mma_bf16(float* c, const unsigned* a,
                                         unsigned b0, unsigned b1) {
    asm volatile(
        "mma.sync.aligned.m16n8k16.row.col.f32.bf16.bf16.f32 "
        "{%0,%1,%2,%3}, {%4,%5,%6,%7}, {%8,%9}, {%0,%1,%2,%3};"
        : "+f"(c[0]), "+f"(c[1]), "+f"(c[2]), "+f"(c[3])
        : "r"(a[0]), "r"(a[1]), "r"(a[2]), "r"(a[3]), "r"(b0), "r"(b1));
}

// Scratch for projected Q, K (layout [b][h][s][d]) and V (TRANSPOSED:
// [b][h][d][s]) in fp32. 16 MB each.
__device__ float g_Q[BATCH * CDIM * SEQ];
__device__ float g_K[BATCH * CDIM * SEQ];
__device__ float g_V[BATCH * CDIM * SEQ];

// ---------------------------------------------------------------------------
// Projection GEMM on tensor cores (3xTF32 mma.sync, ~fp32 accuracy).
// Identical to round-15 version except: the V projection (proj==2) is written
// TRANSPOSED to g_V as [b][h][d][s] so attention can consume V^T directly.
// ---------------------------------------------------------------------------
#define PJ_STRIDE 136
#define PJ_ARR    (16 * PJ_STRIDE)
#define PJ_BUF    (4 * PJ_ARR)
#define PJ_SMEM_WORDS (2 * PJ_BUF)

__global__ void __launch_bounds__(256)
proj_mma_kernel(const float* __restrict__ q_in,
                const float* __restrict__ kv_in,
                const float* __restrict__ W,
                const float* __restrict__ bias)
{
    extern __shared__ unsigned psm[];

    const int nb = blockIdx.x;                 // 0..11
    const int mb = blockIdx.y;                 // 0..63
    const int proj = nb >> 2;
    const float* src = (proj == 0) ? q_in : kv_in;
    float* dst = (proj == 0) ? g_Q : ((proj == 1) ? g_K : g_V);

    const int tid  = threadIdx.x;
    const int lane = tid & 31;
    const int warp = tid >> 5;
    const int g    = lane >> 2;
    const int t4   = lane & 3;

    const int warp_m = (warp >> 2) * 64;
    const int warp_n = (warp & 3) * 32;

    const int b  = mb >> 3;
    const int s0 = (mb & 7) << 7;
    const int n0 = nb << 7;

    const float* Abase = src + b * (CDIM * SEQ) + s0;
    const float* Bbase = W + n0;

    const int ka = tid >> 5;
    const int ma = (tid & 31) << 2;

    float c[4][4][4];
#pragma unroll
    for (int mt = 0; mt < 4; mt++)
#pragma unroll
        for (int nt = 0; nt < 4; nt++)
#pragma unroll
            for (int r = 0; r < 4; r++) c[mt][nt][r] = 0.0f;

    float4 av0 = *(const float4*)(Abase + ka * SEQ + ma);
    float4 av1 = *(const float4*)(Abase + (ka + 8) * SEQ + ma);
    float4 bv0 = *(const float4*)(Bbase + ka * (3 * CDIM) + ma);
    float4 bv1 = *(const float4*)(Bbase + (ka + 8) * (3 * CDIM) + ma);

    int buf = 0;
    for (int k0 = 0; k0 < CDIM; k0 += 16, buf ^= 1) {
        unsigned* Ah = psm + buf * PJ_BUF;
        unsigned* Al = Ah + PJ_ARR;
        unsigned* Bh = Al + PJ_ARR;
        unsigned* Bl = Bh + PJ_ARR;
        {
            uint4 h, l;
            tf32_split(av0.x, h.x, l.x); tf32_split(av0.y, h.y, l.y);
            tf32_split(av0.z, h.z, l.z); tf32_split(av0.w, h.w, l.w);
            *(uint4*)&Ah[ka * PJ_STRIDE + ma] = h;
            *(uint4*)&Al[ka * PJ_STRIDE + ma] = l;
            tf32_split(av1.x, h.x, l.x); tf32_split(av1.y, h.y, l.y);
            tf32_split(av1.z, h.z, l.z); tf32_split(av1.w, h.w, l.w);
            *(uint4*)&Ah[(ka + 8) * PJ_STRIDE + ma] = h;
            *(uint4*)&Al[(ka + 8) * PJ_STRIDE + ma] = l;
            tf32_split(bv0.x, h.x, l.x); tf32_split(bv0.y, h.y, l.y);
            tf32_split(bv0.z, h.z, l.z); tf32_split(bv0.w, h.w, l.w);
            *(uint4*)&Bh[ka * PJ_STRIDE + ma] = h;
            *(uint4*)&Bl[ka * PJ_STRIDE + ma] = l;
            tf32_split(bv1.x, h.x, l.x); tf32_split(bv1.y, h.y, l.y);
            tf32_split(bv1.z, h.z, l.z); tf32_split(bv1.w, h.w, l.w);
            *(uint4*)&Bh[(ka + 8) * PJ_STRIDE + ma] = h;
            *(uint4*)&Bl[(ka + 8) * PJ_STRIDE + ma] = l;
        }
        __syncthreads();

        if (k0 + 16 < CDIM) {
            av0 = *(const float4*)(Abase + (k0 + 16 + ka) * SEQ + ma);
            av1 = *(const float4*)(Abase + (k0 + 24 + ka) * SEQ + ma);
            bv0 = *(const float4*)(Bbase + (k0 + 16 + ka) * (3 * CDIM) + ma);
            bv1 = *(const float4*)(Bbase + (k0 + 24 + ka) * (3 * CDIM) + ma);
        }

#pragma unroll
        for (int ks = 0; ks < 2; ks++) {
            const int kb = ks * 8;
            unsigned bh[4][2], bl[4][2];
            const int bcol = warp_n + g;
#pragma unroll
            for (int nt = 0; nt < 4; nt++) {
                bh[nt][0] = Bh[(kb + t4) * PJ_STRIDE + bcol + nt * 8];
                bh[nt][1] = Bh[(kb + t4 + 4) * PJ_STRIDE + bcol + nt * 8];
                bl[nt][0] = Bl[(kb + t4) * PJ_STRIDE + bcol + nt * 8];
                bl[nt][1] = Bl[(kb + t4 + 4) * PJ_STRIDE + bcol + nt * 8];
            }
            const int arow = warp_m + g;
#pragma unroll
            for (int mt = 0; mt < 4; mt++) {
                unsigned ah[4], al[4];
                ah[0] = Ah[(kb + t4) * PJ_STRIDE + arow + mt * 16];
                ah[1] = Ah[(kb + t4) * PJ_STRIDE + arow + mt * 16 + 8];
                ah[2] = Ah[(kb + t4 + 4) * PJ_STRIDE + arow + mt * 16];
                ah[3] = Ah[(kb + t4 + 4) * PJ_STRIDE + arow + mt * 16 + 8];
                al[0] = Al[(kb + t4) * PJ_STRIDE + arow + mt * 16];
                al[1] = Al[(kb + t4) * PJ_STRIDE + arow + mt * 16 + 8];
                al[2] = Al[(kb + t4 + 4) * PJ_STRIDE + arow + mt * 16];
                al[3] = Al[(kb + t4 + 4) * PJ_STRIDE + arow + mt * 16 + 8];
#pragma unroll
                for (int nt = 0; nt < 4; nt++) {
                    mma_tf32(c[mt][nt], ah, bh[nt]);
                    mma_tf32(c[mt][nt], ah, bl[nt]);
                    mma_tf32(c[mt][nt], al, bh[nt]);
                }
            }
        }
        __syncthreads();
    }

    // Epilogue
#pragma unroll
    for (int nt = 0; nt < 4; nt++) {
        const int n_g = n0 + warp_n + nt * 8 + 2 * t4;
        const int nn  = n_g & 511;
        const int h   = nn >> 6, d = nn & 63;
        const float bx = bias[n_g], by = bias[n_g + 1];
        if (proj != 2) {
            float* op = dst + b * (CDIM * SEQ) + h * (SEQ * HDIM) + d;
#pragma unroll
            for (int mt = 0; mt < 4; mt++) {
                const int srow = s0 + warp_m + mt * 16 + g;
                float2 v0 = { c[mt][nt][0] + bx, c[mt][nt][1] + by };
                float2 v1 = { c[mt][nt][2] + bx, c[mt][nt][3] + by };
                *(float2*)(op + srow * HDIM)       = v0;
                *(float2*)(op + (srow + 8) * HDIM) = v1;
            }
        } else {
            // V: store transposed [b][h][d][s]
            float* op = dst + b * (CDIM * SEQ) + h * (SEQ * HDIM) + d * SEQ;
#pragma unroll
            for (int mt = 0; mt < 4; mt++) {
                const int srow = s0 + warp_m + mt * 16 + g;
                op[srow]           = c[mt][nt][0] + bx;
                op[SEQ + srow]     = c[mt][nt][1] + by;
                op[srow + 8]       = c[mt][nt][2] + bx;
                op[SEQ + srow + 8] = c[mt][nt][3] + by;
            }
        }
    }
}

// ---------------------------------------------------------------------------
// Flash attention on tensor cores (bf16 2-term split, 3 mma per product).
// 128 threads (4 warps); warp w owns q-rows [16w,16w+16); tiles 64x64.
//  - Q fragments: registers, whole kernel (split once, scaled by SCALE*log2e)
//  - K tile: bf16 hi/lo words [key][d-pair], word-stride 36 (banks 4g+t4,
//    conflict-free fragment loads)
//  - V tile: read from g_V (already [d][s] transposed), same bf16 layout
//    [d][key-pair] stride 36
//  - P: formed in registers from S's C-fragments (C cols 2t4,2t4+1 == A-frag
//    k-pairs) -> no smem staging, no extra barriers
// Smem: Khi/Klo/Vhi/Vlo 4 x 2304 words = 36,864 B; epilogue O^T aliases Khi.
// ---------------------------------------------------------------------------
#define AKV_WS  36
#define AKV_ARR (64 * AKV_WS)                 // 2304 words
#define ATTN_SMEM_WORDS (4 * AKV_ARR)         // 9216 words = 36,864 B

__global__ void __launch_bounds__(128)
attn_kernel(float* __restrict__ out)
{
    extern __shared__ unsigned smu[];
    unsigned* Khi = smu;
    unsigned* Klo = smu + AKV_ARR;
    unsigned* Vhi = smu + 2 * AKV_ARR;
    unsigned* Vlo = smu + 3 * AKV_ARR;

    const int tid  = threadIdx.x;
    const int lane = tid & 31;
    const int warp = tid >> 5;
    const int g    = lane >> 2;
    const int t4   = lane & 3;

    const int bh = blockIdx.y;
    const int q0 = blockIdx.x << 6;
    const float* Qp = g_Q + bh * (SEQ * HDIM);
    const float* Kp = g_K + bh * (SEQ * HDIM);
    const float* Vp = g_V + bh * (SEQ * HDIM);   // [d][s] layout

    const float qscale = SCALE * LOG2E;

    // ---- Q fragments in registers (fixed) ----
    unsigned qh[4][4], ql[4][4];
    {
        const float* Qr0 = Qp + (q0 + warp * 16 + g) * HDIM;
        const float* Qr8 = Qr0 + 8 * HDIM;
#pragma unroll
        for (int ks = 0; ks < 4; ks++) {
            float2 x0 = *(const float2*)(Qr0 + ks * 16 + 2 * t4);
            float2 x1 = *(const float2*)(Qr8 + ks * 16 + 2 * t4);
            float2 x2 = *(const float2*)(Qr0 + ks * 16 + 2 * t4 + 8);
            float2 x3 = *(const float2*)(Qr8 + ks * 16 + 2 * t4 + 8);
            bsplit2(x0.x * qscale, x0.y * qscale, qh[ks][0], ql[ks][0]);
            bsplit2(x1.x * qscale, x1.y * qscale, qh[ks][1], ql[ks][1]);
            bsplit2(x2.x * qscale, x2.y * qscale, qh[ks][2], ql[ks][2]);
            bsplit2(x3.x * qscale, x3.y * qscale, qh[ks][3], ql[ks][3]);
        }
    }

    float o[8][4];
#pragma unroll
    for (int nt = 0; nt < 8; nt++)
#pragma unroll
        for (int r = 0; r < 4; r++) o[nt][r] = 0.0f;
    float m0 = -1e30f, m1 = -1e30f, l0 = 0.0f, l1 = 0.0f;

    for (int kt = 0; kt < 16; kt++) {
        const int key0 = kt << 6;
        __syncthreads();            // previous iteration's smem reads done

        // ---- load & bf16-split K and V^T tiles ----
#pragma unroll
        for (int it = 0; it < 8; it++) {
            const int id = tid + it * 128;
            const int r  = id >> 4;            // key row (K) / d row (V)
            const int c0 = (id & 15) << 2;     // d (K) / key (V)
            unsigned h01, l01, h23, l23;
            float4 kv = *(const float4*)(Kp + (key0 + r) * HDIM + c0);
            bsplit2(kv.x, kv.y, h01, l01);
            bsplit2(kv.z, kv.w, h23, l23);
            Khi[r * AKV_WS + (c0 >> 1)]     = h01;
            Khi[r * AKV_WS + (c0 >> 1) + 1] = h23;
            Klo[r * AKV_WS + (c0 >> 1)]     = l01;
            Klo[r * AKV_WS + (c0 >> 1) + 1] = l23;
            float4 vv = *(const float4*)(Vp + r * SEQ + key0 + c0);
            bsplit2(vv.x, vv.y, h01, l01);
            bsplit2(vv.z, vv.w, h23, l23);
            Vhi[r * AKV_WS + (c0 >> 1)]     = h01;
            Vhi[r * AKV_WS + (c0 >> 1) + 1] = h23;
            Vlo[r * AKV_WS + (c0 >> 1)]     = l01;
            Vlo[r * AKV_WS + (c0 >> 1) + 1] = l23;
        }
        __syncthreads();

        // ---- S = Q K^T (exp2 domain) ----
        float c[8][4];
#pragma unroll
        for (int nt = 0; nt < 8; nt++)
#pragma unroll
            for (int r = 0; r < 4; r++) c[nt][r] = 0.0f;

#pragma unroll
        for (int ks = 0; ks < 4; ks++) {
#pragma unroll
            for (int nt = 0; nt < 8; nt++) {
                const unsigned* kb = Khi + (nt * 8 + g) * AKV_WS + ks * 8 + t4;
                const unsigned* kl = Klo + (nt * 8 + g) * AKV_WS + ks * 8 + t4;
                unsigned bh0 = kb[0], bh1 = kb[4];
                unsigned bl0 = kl[0], bl1 = kl[4];
                mma_bf16(c[nt], qh[ks], bh0, bh1);
                mma_bf16(c[nt], qh[ks], bl0, bl1);
                mma_bf16(c[nt], ql[ks], bh0, bh1);
            }
        }

        // ---- online softmax (2 rows/thread: g and g+8) ----
        float cm0 = c[0][0], cm1 = c[0][2];
#pragma unroll
        for (int nt = 0; nt < 8; nt++) {
            cm0 = fmaxf(cm0, fmaxf(c[nt][0], c[nt][1]));
            cm1 = fmaxf(cm1, fmaxf(c[nt][2], c[nt][3]));
        }
        cm0 = fmaxf(cm0, __shfl_xor_sync(0xffffffffu, cm0, 1));
        cm0 = fmaxf(cm0, __shfl_xor_sync(0xffffffffu, cm0, 2));
        cm1 = fmaxf(cm1, __shfl_xor_sync(0xffffffffu, cm1, 1));
        cm1 = fmaxf(cm1, __shfl_xor_sync(0xffffffffu, cm1, 2));

        const float mn0 = fmaxf(m0, cm0), mn1 = fmaxf(m1, cm1);
        const float a0 = ex2(m0 - mn0), a1 = ex2(m1 - mn1);
        m0 = mn0; m1 = mn1;

        float s0 = 0.0f, s1 = 0.0f;
#pragma unroll
        for (int nt = 0; nt < 8; nt++) {
            c[nt][0] = ex2(c[nt][0] - m0);
            c[nt][1] = ex2(c[nt][1] - m0);
            c[nt][2] = ex2(c[nt][2] - m1);
            c[nt][3] = ex2(c[nt][3] - m1);
            s0 += c[nt][0] + c[nt][1];
            s1 += c[nt][2] + c[nt][3];
        }
        s0 += __shfl_xor_sync(0xffffffffu, s0, 1);
        s0 += __shfl_xor_sync(0xffffffffu, s0, 2);
        s1 += __shfl_xor_sync(0xffffffffu, s1, 1);
        s1 += __shfl_xor_sync(0xffffffffu, s1, 2);
        l0 = l0 * a0 + s0;
        l1 = l1 * a1 + s1;
#pragma unroll
        for (int nt = 0; nt < 8; nt++) {
            o[nt][0] *= a0; o[nt][1] *= a0;
            o[nt][2] *= a1; o[nt][3] *= a1;
        }

        // ---- O += P V : P fragments formed in registers ----
#pragma unroll
        for (int ks = 0; ks < 4; ks++) {
            unsigned ph[4], pl[4];
            bsplit2(c[2*ks][0],   c[2*ks][1],   ph[0], pl[0]);
            bsplit2(c[2*ks][2],   c[2*ks][3],   ph[1], pl[1]);
            bsplit2(c[2*ks+1][0], c[2*ks+1][1], ph[2], pl[2]);
            bsplit2(c[2*ks+1][2], c[2*ks+1][3], ph[3], pl[3]);
#pragma unroll
            for (int nt = 0; nt < 8; nt++) {
                const unsigned* vb = Vhi + (nt * 8 + g) * AKV_WS + ks * 8 + t4;
                const unsigned* vl = Vlo + (nt * 8 + g) * AKV_WS + ks * 8 + t4;
                unsigned bh0 = vb[0], bh1 = vb[4];
                unsigned bl0 = vl[0], bl1 = vl[4];
                mma_bf16(o[nt], ph, bh0, bh1);
                mma_bf16(o[nt], ph, bl0, bl1);
                mma_bf16(o[nt], pl, bh0, bh1);
            }
        }
    }

    // ---- normalize & epilogue (O^T via smem, coalesced [b][c][s] stores) ----
    const float inv0 = 1.0f / l0, inv1 = 1.0f / l1;
#pragma unroll
    for (int nt = 0; nt < 8; nt++) {
        o[nt][0] *= inv0; o[nt][1] *= inv0;
        o[nt][2] *= inv1; o[nt][3] *= inv1;
    }

    float* Ot = (float*)smu;        // [64 d][stride 68], aliases K region
    __syncthreads();                // all smem reads of last tile complete
#pragma unroll
    for (int nt = 0; nt < 8; nt++) {
        const int d = nt * 8 + 2 * t4;
        const int r = warp * 16 + g;
        Ot[d * 68 + r]           = o[nt][0];
        Ot[(d + 1) * 68 + r]     = o[nt][1];
        Ot[d * 68 + r + 8]       = o[nt][2];
        Ot[(d + 1) * 68 + r + 8] = o[nt][3];
    }
    __syncthreads();

    const int b = bh >> 3, h = bh & 7;
    float* obase = out + b * (CDIM * SEQ) + (h * HDIM) * SEQ + q0;
#pragma unroll
    for (int it = 0; it < 8; it++) {
        const int id = tid + it * 128;
        const int d  = id >> 4;
        const int r0 = (id & 15) << 2;
        float4 v = *(const float4*)(Ot + d * 68 + r0);
        *(float4*)(obase + d * SEQ + r0) = v;
    }
}

// ---------------------------------------------------------------------------
extern "C" void kernel_launch(void* const* d_in, const int* in_sizes, int n_in,
                              void* d_out, int out_size)
{
    const float* q_in  = (const float*)d_in[0];   // query     [8,512,32,32]
    const float* kv_in = (const float*)d_in[1];   // key_value [8,512,32,32]
    const float* W     = (const float*)d_in[2];   // W_qkv     [512,1536]
    const float* bias  = (const float*)d_in[3];   // b_qkv     [1536]
    float* out = (float*)d_out;

    cudaFuncSetAttribute(proj_mma_kernel,
                         cudaFuncAttributeMaxDynamicSharedMemorySize,
                         PJ_SMEM_WORDS * (int)sizeof(unsigned));
    cudaFuncSetAttribute(attn_kernel,
                         cudaFuncAttributeMaxDynamicSharedMemorySize,
                         ATTN_SMEM_WORDS * (int)sizeof(unsigned));

    proj_mma_kernel<<<dim3(12, 64), 256, PJ_SMEM_WORDS * sizeof(unsigned)>>>(
        q_in, kv_in, W, bias);
    attn_kernel<<<dim3(16, 64), 128, ATTN_SMEM_WORDS * sizeof(unsigned)>>>(out);
}

// round 17
// speedup vs baseline: 2.6656x; 1.4294x over previous
#include <cuda_runtime.h>

// Problem constants
#define BATCH   8
#define CDIM    512
#define SEQ     1024      // H*W = 32*32
#define NHEADS  8
#define HDIM    64
#define SCALE   0.125f    // 1/sqrt(64)
#define LOG2E   1.44269504088896340736f

__device__ __forceinline__ float ex2(float x) {
    float r; asm("ex2.approx.f32 %0, %1;" : "=f"(r) : "f"(x)); return r;
}

// bf16 helpers: pack two floats into bf16x2 (first elem -> low half)
__device__ __forceinline__ unsigned packbf(float first, float second) {
    unsigned r;
    asm("cvt.rn.bf16x2.f32 %0, %1, %2;" : "=r"(r) : "f"(second), "f"(first));
    return r;
}
// 2-term bf16 split of a pair: h = bf16x2(x,y), l = bf16x2 of residuals
__device__ __forceinline__ void bsplit2(float x, float y, unsigned &h, unsigned &l) {
    h = packbf(x, y);
    float rx = x - __uint_as_float(h << 16);
    float ry = y - __uint_as_float(h & 0xffff0000u);
    l = packbf(rx, ry);
}

__device__ __forceinline__ void mma_bf16(float* c, const unsigned* a,
                                         unsigned b0, unsigned b1) {
    asm volatile(
        "mma.sync.aligned.m16n8k16.row.col.f32.bf16.bf16.f32 "
        "{%0,%1,%2,%3}, {%4,%5,%6,%7}, {%8,%9}, {%0,%1,%2,%3};"
        : "+f"(c[0]), "+f"(c[1]), "+f"(c[2]), "+f"(c[3])
        : "r"(a[0]), "r"(a[1]), "r"(a[2]), "r"(a[3]), "r"(b0), "r"(b1));
}

// Scratch for projected Q, K (layout [b][h][s][d]) and V (TRANSPOSED:
// [b][h][d][s]) in fp32. 16 MB each.
__device__ float g_Q[BATCH * CDIM * SEQ];
__device__ float g_K[BATCH * CDIM * SEQ];
__device__ float g_V[BATCH * CDIM * SEQ];

// ---------------------------------------------------------------------------
// Projection GEMM on tensor cores, bf16 2-term split (3 x m16n8k16 per
// product, ~fp32 accuracy ~2^-16).
//   C[m][n] = sum_k A[m][k] * W[k][n];  A[m][k] = src[b][k][s] (coalesced).
//   Block 256 thr (8 warps), tile M=128 x N=128, K-stage 16, double-buffered.
//   Smem: k-pair words w[kp][m] = bf16x2(X[2kp][m], X[2kp+1][m]), kp=0..7,
//   word-stride 136 (== 8 mod 32) -> fragment reads hit banks 8*t4+g:
//   a 32-permutation, conflict-free. Global loader reads two consecutive
//   k-rows per thread (float4) and packs pairs in registers.
//   V projection (proj==2) written TRANSPOSED to g_V as [b][h][d][s].
// ---------------------------------------------------------------------------
#define PJ_STRIDE 136
#define PJ_ARR    (8 * PJ_STRIDE)           // 1088 words per array
#define PJ_BUF    (4 * PJ_ARR)              // Ahi, Alo, Bhi, Blo
#define PJ_SMEM_WORDS (2 * PJ_BUF)          // 8704 words = 34,816 B

__global__ void __launch_bounds__(256)
proj_mma_kernel(const float* __restrict__ q_in,
                const float* __restrict__ kv_in,
                const float* __restrict__ W,
                const float* __restrict__ bias)
{
    extern __shared__ unsigned psm[];

    const int nb = blockIdx.x;                 // 0..11
    const int mb = blockIdx.y;                 // 0..63
    const int proj = nb >> 2;
    const float* src = (proj == 0) ? q_in : kv_in;
    float* dst = (proj == 0) ? g_Q : ((proj == 1) ? g_K : g_V);

    const int tid  = threadIdx.x;
    const int lane = tid & 31;
    const int warp = tid >> 5;
    const int g    = lane >> 2;
    const int t4   = lane & 3;

    const int warp_m = (warp >> 2) * 64;
    const int warp_n = (warp & 3) * 32;

    const int b  = mb >> 3;
    const int s0 = (mb & 7) << 7;
    const int n0 = nb << 7;

    const float* Abase = src + b * (CDIM * SEQ) + s0;
    const float* Bbase = W + n0;

    const int ka = tid >> 5;                   // 0..7 (k-pair row)
    const int ma = (tid & 31) << 2;            // 0..124

    float c[4][4][4];
#pragma unroll
    for (int mt = 0; mt < 4; mt++)
#pragma unroll
        for (int nt = 0; nt < 4; nt++)
#pragma unroll
            for (int r = 0; r < 4; r++) c[mt][nt][r] = 0.0f;

    // preload stage 0: two consecutive k-rows per thread
    float4 av0 = *(const float4*)(Abase + (2 * ka) * SEQ + ma);
    float4 av1 = *(const float4*)(Abase + (2 * ka + 1) * SEQ + ma);
    float4 bv0 = *(const float4*)(Bbase + (2 * ka) * (3 * CDIM) + ma);
    float4 bv1 = *(const float4*)(Bbase + (2 * ka + 1) * (3 * CDIM) + ma);

    int buf = 0;
    for (int k0 = 0; k0 < CDIM; k0 += 16, buf ^= 1) {
        unsigned* Ahi = psm + buf * PJ_BUF;
        unsigned* Alo = Ahi + PJ_ARR;
        unsigned* Bhi = Alo + PJ_ARR;
        unsigned* Blo = Bhi + PJ_ARR;

        {   // pack k-pairs along k: w = bf16x2(row 2ka, row 2ka+1)
            uint4 hw, lw;
            bsplit2(av0.x, av1.x, hw.x, lw.x);
            bsplit2(av0.y, av1.y, hw.y, lw.y);
            bsplit2(av0.z, av1.z, hw.z, lw.z);
            bsplit2(av0.w, av1.w, hw.w, lw.w);
            *(uint4*)&Ahi[ka * PJ_STRIDE + ma] = hw;
            *(uint4*)&Alo[ka * PJ_STRIDE + ma] = lw;
            bsplit2(bv0.x, bv1.x, hw.x, lw.x);
            bsplit2(bv0.y, bv1.y, hw.y, lw.y);
            bsplit2(bv0.z, bv1.z, hw.z, lw.z);
            bsplit2(bv0.w, bv1.w, hw.w, lw.w);
            *(uint4*)&Bhi[ka * PJ_STRIDE + ma] = hw;
            *(uint4*)&Blo[ka * PJ_STRIDE + ma] = lw;
        }
        __syncthreads();

        if (k0 + 16 < CDIM) {                  // prefetch next stage
            av0 = *(const float4*)(Abase + (k0 + 16 + 2 * ka) * SEQ + ma);
            av1 = *(const float4*)(Abase + (k0 + 17 + 2 * ka) * SEQ + ma);
            bv0 = *(const float4*)(Bbase + (k0 + 16 + 2 * ka) * (3 * CDIM) + ma);
            bv1 = *(const float4*)(Bbase + (k0 + 17 + 2 * ka) * (3 * CDIM) + ma);
        }

        // ---- one k16 step: 16 frag-tiles x 3 mma ----
        {
            const int bcol = warp_n + g;
            unsigned bh0[4], bh1[4], bl0[4], bl1[4];
#pragma unroll
            for (int nt = 0; nt < 4; nt++) {
                bh0[nt] = Bhi[t4 * PJ_STRIDE + bcol + nt * 8];
                bh1[nt] = Bhi[(t4 + 4) * PJ_STRIDE + bcol + nt * 8];
                bl0[nt] = Blo[t4 * PJ_STRIDE + bcol + nt * 8];
                bl1[nt] = Blo[(t4 + 4) * PJ_STRIDE + bcol + nt * 8];
            }
            const int arow = warp_m + g;
#pragma unroll
            for (int mt = 0; mt < 4; mt++) {
                unsigned ah[4], al[4];
                ah[0] = Ahi[t4 * PJ_STRIDE + arow + mt * 16];
                ah[1] = Ahi[t4 * PJ_STRIDE + arow + mt * 16 + 8];
                ah[2] = Ahi[(t4 + 4) * PJ_STRIDE + arow + mt * 16];
                ah[3] = Ahi[(t4 + 4) * PJ_STRIDE + arow + mt * 16 + 8];
                al[0] = Alo[t4 * PJ_STRIDE + arow + mt * 16];
                al[1] = Alo[t4 * PJ_STRIDE + arow + mt * 16 + 8];
                al[2] = Alo[(t4 + 4) * PJ_STRIDE + arow + mt * 16];
                al[3] = Alo[(t4 + 4) * PJ_STRIDE + arow + mt * 16 + 8];
#pragma unroll
                for (int nt = 0; nt < 4; nt++) {
                    mma_bf16(c[mt][nt], ah, bh0[nt], bh1[nt]);   // hi*hi
                    mma_bf16(c[mt][nt], ah, bl0[nt], bl1[nt]);   // hi*lo
                    mma_bf16(c[mt][nt], al, bh0[nt], bh1[nt]);   // lo*hi
                }
            }
        }
        __syncthreads();
    }

    // Epilogue: C frag c0=(g, 2t4), c1=(g, 2t4+1), c2=(g+8, 2t4), c3=(g+8, 2t4+1)
#pragma unroll
    for (int nt = 0; nt < 4; nt++) {
        const int n_g = n0 + warp_n + nt * 8 + 2 * t4;
        const int nn  = n_g & 511;
        const int h   = nn >> 6, d = nn & 63;
        const float bx = bias[n_g], by = bias[n_g + 1];
        if (proj != 2) {
            float* op = dst + b * (CDIM * SEQ) + h * (SEQ * HDIM) + d;
#pragma unroll
            for (int mt = 0; mt < 4; mt++) {
                const int srow = s0 + warp_m + mt * 16 + g;
                float2 v0 = { c[mt][nt][0] + bx, c[mt][nt][1] + by };
                float2 v1 = { c[mt][nt][2] + bx, c[mt][nt][3] + by };
                *(float2*)(op + srow * HDIM)       = v0;
                *(float2*)(op + (srow + 8) * HDIM) = v1;
            }
        } else {
            // V: store transposed [b][h][d][s]
            float* op = dst + b * (CDIM * SEQ) + h * (SEQ * HDIM) + d * SEQ;
#pragma unroll
            for (int mt = 0; mt < 4; mt++) {
                const int srow = s0 + warp_m + mt * 16 + g;
                op[srow]           = c[mt][nt][0] + bx;
                op[SEQ + srow]     = c[mt][nt][1] + by;
                op[srow + 8]       = c[mt][nt][2] + bx;
                op[SEQ + srow + 8] = c[mt][nt][3] + by;
            }
        }
    }
}

// ---------------------------------------------------------------------------
// Flash attention on tensor cores (bf16 2-term split, 3 mma per product).
// Round-16 version verbatim (measured 159.8us).
// ---------------------------------------------------------------------------
#define AKV_WS  36
#define AKV_ARR (64 * AKV_WS)                 // 2304 words
#define ATTN_SMEM_WORDS (4 * AKV_ARR)         // 9216 words = 36,864 B

__global__ void __launch_bounds__(128)
attn_kernel(float* __restrict__ out)
{
    extern __shared__ unsigned smu[];
    unsigned* Khi = smu;
    unsigned* Klo = smu + AKV_ARR;
    unsigned* Vhi = smu + 2 * AKV_ARR;
    unsigned* Vlo = smu + 3 * AKV_ARR;

    const int tid  = threadIdx.x;
    const int lane = tid & 31;
    const int warp = tid >> 5;
    const int g    = lane >> 2;
    const int t4   = lane & 3;

    const int bh = blockIdx.y;
    const int q0 = blockIdx.x << 6;
    const float* Qp = g_Q + bh * (SEQ * HDIM);
    const float* Kp = g_K + bh * (SEQ * HDIM);
    const float* Vp = g_V + bh * (SEQ * HDIM);   // [d][s] layout

    const float qscale = SCALE * LOG2E;

    // ---- Q fragments in registers (fixed) ----
    unsigned qh[4][4], ql[4][4];
    {
        const float* Qr0 = Qp + (q0 + warp * 16 + g) * HDIM;
        const float* Qr8 = Qr0 + 8 * HDIM;
#pragma unroll
        for (int ks = 0; ks < 4; ks++) {
            float2 x0 = *(const float2*)(Qr0 + ks * 16 + 2 * t4);
            float2 x1 = *(const float2*)(Qr8 + ks * 16 + 2 * t4);
            float2 x2 = *(const float2*)(Qr0 + ks * 16 + 2 * t4 + 8);
            float2 x3 = *(const float2*)(Qr8 + ks * 16 + 2 * t4 + 8);
            bsplit2(x0.x * qscale, x0.y * qscale, qh[ks][0], ql[ks][0]);
            bsplit2(x1.x * qscale, x1.y * qscale, qh[ks][1], ql[ks][1]);
            bsplit2(x2.x * qscale, x2.y * qscale, qh[ks][2], ql[ks][2]);
            bsplit2(x3.x * qscale, x3.y * qscale, qh[ks][3], ql[ks][3]);
        }
    }

    float o[8][4];
#pragma unroll
    for (int nt = 0; nt < 8; nt++)
#pragma unroll
        for (int r = 0; r < 4; r++) o[nt][r] = 0.0f;
    float m0 = -1e30f, m1 = -1e30f, l0 = 0.0f, l1 = 0.0f;

    for (int kt = 0; kt < 16; kt++) {
        const int key0 = kt << 6;
        __syncthreads();            // previous iteration's smem reads done

        // ---- load & bf16-split K and V^T tiles ----
#pragma unroll
        for (int it = 0; it < 8; it++) {
            const int id = tid + it * 128;
            const int r  = id >> 4;            // key row (K) / d row (V)
            const int c0 = (id & 15) << 2;     // d (K) / key (V)
            unsigned h01, l01, h23, l23;
            float4 kv = *(const float4*)(Kp + (key0 + r) * HDIM + c0);
            bsplit2(kv.x, kv.y, h01, l01);
            bsplit2(kv.z, kv.w, h23, l23);
            Khi[r * AKV_WS + (c0 >> 1)]     = h01;
            Khi[r * AKV_WS + (c0 >> 1) + 1] = h23;
            Klo[r * AKV_WS + (c0 >> 1)]     = l01;
            Klo[r * AKV_WS + (c0 >> 1) + 1] = l23;
            float4 vv = *(const float4*)(Vp + r * SEQ + key0 + c0);
            bsplit2(vv.x, vv.y, h01, l01);
            bsplit2(vv.z, vv.w, h23, l23);
            Vhi[r * AKV_WS + (c0 >> 1)]     = h01;
            Vhi[r * AKV_WS + (c0 >> 1) + 1] = h23;
            Vlo[r * AKV_WS + (c0 >> 1)]     = l01;
            Vlo[r * AKV_WS + (c0 >> 1) + 1] = l23;
        }
        __syncthreads();

        // ---- S = Q K^T (exp2 domain) ----
        float c[8][4];
#pragma unroll
        for (int nt = 0; nt < 8; nt++)
#pragma unroll
            for (int r = 0; r < 4; r++) c[nt][r] = 0.0f;

#pragma unroll
        for (int ks = 0; ks < 4; ks++) {
#pragma unroll
            for (int nt = 0; nt < 8; nt++) {
                const unsigned* kb = Khi + (nt * 8 + g) * AKV_WS + ks * 8 + t4;
                const unsigned* kl = Klo + (nt * 8 + g) * AKV_WS + ks * 8 + t4;
                unsigned bh0 = kb[0], bh1 = kb[4];
                unsigned bl0 = kl[0], bl1 = kl[4];
                mma_bf16(c[nt], qh[ks], bh0, bh1);
                mma_bf16(c[nt], qh[ks], bl0, bl1);
                mma_bf16(c[nt], ql[ks], bh0, bh1);
            }
        }

        // ---- online softmax (2 rows/thread: g and g+8) ----
        float cm0 = c[0][0], cm1 = c[0][2];
#pragma unroll
        for (int nt = 0; nt < 8; nt++) {
            cm0 = fmaxf(cm0, fmaxf(c[nt][0], c[nt][1]));
            cm1 = fmaxf(cm1, fmaxf(c[nt][2], c[nt][3]));
        }
        cm0 = fmaxf(cm0, __shfl_xor_sync(0xffffffffu, cm0, 1));
        cm0 = fmaxf(cm0, __shfl_xor_sync(0xffffffffu, cm0, 2));
        cm1 = fmaxf(cm1, __shfl_xor_sync(0xffffffffu, cm1, 1));
        cm1 = fmaxf(cm1, __shfl_xor_sync(0xffffffffu, cm1, 2));

        const float mn0 = fmaxf(m0, cm0), mn1 = fmaxf(m1, cm1);
        const float a0 = ex2(m0 - mn0), a1 = ex2(m1 - mn1);
        m0 = mn0; m1 = mn1;

        float s0 = 0.0f, s1 = 0.0f;
#pragma unroll
        for (int nt = 0; nt < 8; nt++) {
            c[nt][0] = ex2(c[nt][0] - m0);
            c[nt][1] = ex2(c[nt][1] - m0);
            c[nt][2] = ex2(c[nt][2] - m1);
            c[nt][3] = ex2(c[nt][3] - m1);
            s0 += c[nt][0] + c[nt][1];
            s1 += c[nt][2] + c[nt][3];
        }
        s0 += __shfl_xor_sync(0xffffffffu, s0, 1);
        s0 += __shfl_xor_sync(0xffffffffu, s0, 2);
        s1 += __shfl_xor_sync(0xffffffffu, s1, 1);
        s1 += __shfl_xor_sync(0xffffffffu, s1, 2);
        l0 = l0 * a0 + s0;
        l1 = l1 * a1 + s1;
#pragma unroll
        for (int nt = 0; nt < 8; nt++) {
            o[nt][0] *= a0; o[nt][1] *= a0;
            o[nt][2] *= a1; o[nt][3] *= a1;
        }

        // ---- O += P V : P fragments formed in registers ----
#pragma unroll
        for (int ks = 0; ks < 4; ks++) {
            unsigned ph[4], pl[4];
            bsplit2(c[2*ks][0],   c[2*ks][1],   ph[0], pl[0]);
            bsplit2(c[2*ks][2],   c[2*ks][3],   ph[1], pl[1]);
            bsplit2(c[2*ks+1][0], c[2*ks+1][1], ph[2], pl[2]);
            bsplit2(c[2*ks+1][2], c[2*ks+1][3], ph[3], pl[3]);
#pragma unroll
            for (int nt = 0; nt < 8; nt++) {
                const unsigned* vb = Vhi + (nt * 8 + g) * AKV_WS + ks * 8 + t4;
                const unsigned* vl = Vlo + (nt * 8 + g) * AKV_WS + ks * 8 + t4;
                unsigned bh0 = vb[0], bh1 = vb[4];
                unsigned bl0 = vl[0], bl1 = vl[4];
                mma_bf16(o[nt], ph, bh0, bh1);
                mma_bf16(o[nt], ph, bl0, bl1);
                mma_bf16(o[nt], pl, bh0, bh1);
            }
        }
    }

    // ---- normalize & epilogue (O^T via smem, coalesced [b][c][s] stores) ----
    const float inv0 = 1.0f / l0, inv1 = 1.0f / l1;
#pragma unroll
    for (int nt = 0; nt < 8; nt++) {
        o[nt][0] *= inv0; o[nt][1] *= inv0;
        o[nt][2] *= inv1; o[nt][3] *= inv1;
    }

    float* Ot = (float*)smu;        // [64 d][stride 68], aliases K region
    __syncthreads();                // all smem reads of last tile complete
#pragma unroll
    for (int nt = 0; nt < 8; nt++) {
        const int d = nt * 8 + 2 * t4;
        const int r = warp * 16 + g;
        Ot[d * 68 + r]           = o[nt][0];
        Ot[(d + 1) * 68 + r]     = o[nt][1];
        Ot[d * 68 + r + 8]       = o[nt][2];
        Ot[(d + 1) * 68 + r + 8] = o[nt][3];
    }
    __syncthreads();

    const int b = bh >> 3, h = bh & 7;
    float* obase = out + b * (CDIM * SEQ) + (h * HDIM) * SEQ + q0;
#pragma unroll
    for (int it = 0; it < 8; it++) {
        const int id = tid + it * 128;
        const int d  = id >> 4;
        const int r0 = (id & 15) << 2;
        float4 v = *(const float4*)(Ot + d * 68 + r0);
        *(float4*)(obase + d * SEQ + r0) = v;
    }
}

// ---------------------------------------------------------------------------
extern "C" void kernel_launch(void* const* d_in, const int* in_sizes, int n_in,
                              void* d_out, int out_size)
{
    const float* q_in  = (const float*)d_in[0];   // query     [8,512,32,32]
    const float* kv_in = (const float*)d_in[1];   // key_value [8,512,32,32]
    const float* W     = (const float*)d_in[2];   // W_qkv     [512,1536]
    const float* bias  = (const float*)d_in[3];   // b_qkv     [1536]
    float* out = (float*)d_out;

    cudaFuncSetAttribute(proj_mma_kernel,
                         cudaFuncAttributeMaxDynamicSharedMemorySize,
                         PJ_SMEM_WORDS * (int)sizeof(unsigned));
    cudaFuncSetAttribute(attn_kernel,
                         cudaFuncAttributeMaxDynamicSharedMemorySize,
                         ATTN_SMEM_WORDS * (int)sizeof(unsigned));

    proj_mma_kernel<<<dim3(12, 64), 256, PJ_SMEM_WORDS * sizeof(unsigned)>>>(
        q_in, kv_in, W, bias);
    attn_kernel<<<dim3(16, 64), 128, ATTN_SMEM_WORDS * sizeof(unsigned)>>>(out);
}